// round 15
// baseline (speedup 1.0000x reference)
#include <cuda_runtime.h>
#include <cuda_bf16.h>
#include <cstdint>

// ---------------- problem constants ----------------
#define BB    32
#define PP    14
#define CC    768
#define HH    12
#define HD    64
#define HIDN  3072
#define NWIN  49
#define NPIX  196
#define ROWS  6272         // 32*196

// ---------------- scratch ----------------
__device__ float g_qkv  [(size_t)ROWS * 3 * CC];
__device__ float g_xattn[(size_t)ROWS * CC];
__device__ float g_h1   [(size_t)ROWS * HIDN];
__device__ float g_h2   [(size_t)ROWS * HIDN];
__device__ float g_h3   [(size_t)ROWS * CC];
__device__ float g_s1   [HIDN];
__device__ float g_s2   [HIDN];
__device__ float g_semean [BB * HIDN];
__device__ float g_sehid  [BB * CC];
__device__ float g_sescale[BB * HIDN];
__device__ float g_bnsc [HIDN];
__device__ float g_bnsh [HIDN];
// bf16 split buffers
__device__ __nv_bfloat16 g_ahi[(size_t)ROWS * HIDN];
__device__ __nv_bfloat16 g_alo[(size_t)ROWS * HIDN];
__device__ __nv_bfloat16 g_bhi[(size_t)ROWS * CC];
__device__ __nv_bfloat16 g_blo[(size_t)ROWS * CC];
__device__ __nv_bfloat16 g_whi[(size_t)HIDN * CC];
__device__ __nv_bfloat16 g_wlo[(size_t)HIDN * CC];

__device__ __forceinline__ int reg3(int r) { return r < 7 ? 0 : (r < 11 ? 1 : 2); }
__device__ __forceinline__ float hsw(float x) { return x * __saturatef((x + 3.f) * (1.f / 6.f)); }
__device__ __forceinline__ void split2(float a, float b, uint32_t& hi, uint32_t& lo) {
    __nv_bfloat16 ha = __float2bfloat16(a), hb = __float2bfloat16(b);
    __nv_bfloat16 la = __float2bfloat16(a - __bfloat162float(ha));
    __nv_bfloat16 lb = __float2bfloat16(b - __bfloat162float(hb));
    __nv_bfloat162 H = __halves2bfloat162(ha, hb), L = __halves2bfloat162(la, lb);
    hi = *(uint32_t*)&H; lo = *(uint32_t*)&L;
}
__device__ __forceinline__ uint32_t s2u(const void* p) {
    uint32_t a;
    asm("{ .reg .u64 t; cvta.to.shared.u64 t, %1; cvt.u32.u64 %0, t; }" : "=r"(a) : "l"(p));
    return a;
}
#define CPA16(dst, src) asm volatile("cp.async.cg.shared.global [%0], [%1], 16;" :: "r"(dst), "l"(src) : "memory")
#define CPA_COMMIT()    asm volatile("cp.async.commit_group;" ::: "memory")
#define CPA_WAIT1()     asm volatile("cp.async.wait_group 1;" ::: "memory")
#define CPA_WAIT0()     asm volatile("cp.async.wait_group 0;" ::: "memory")

__device__ __forceinline__ void ldmA(uint32_t* r, uint32_t addr) {
    asm volatile("ldmatrix.sync.aligned.m8n8.x4.shared.b16 {%0,%1,%2,%3}, [%4];"
                 : "=r"(r[0]), "=r"(r[1]), "=r"(r[2]), "=r"(r[3]) : "r"(addr));
}
__device__ __forceinline__ void ldmB(uint32_t* r, uint32_t addr) {
    asm volatile("ldmatrix.sync.aligned.m8n8.x2.shared.b16 {%0,%1}, [%2];"
                 : "=r"(r[0]), "=r"(r[1]) : "r"(addr));
}
__device__ __forceinline__ void mma16816(float* c, const uint32_t* a, const uint32_t* b) {
    asm volatile("mma.sync.aligned.m16n8k16.row.col.f32.bf16.bf16.f32 "
                 "{%0,%1,%2,%3}, {%4,%5,%6,%7}, {%8,%9}, {%0,%1,%2,%3};"
                 : "+f"(c[0]), "+f"(c[1]), "+f"(c[2]), "+f"(c[3])
                 : "r"(a[0]), "r"(a[1]), "r"(a[2]), "r"(a[3]), "r"(b[0]), "r"(b[1]));
}

// ---------------- cls passthrough ----------------
__global__ void k_cls(const float* __restrict__ x, float* __restrict__ out) {
    int i = blockIdx.x * blockDim.x + threadIdx.x;
    if (i >= BB * CC) return;
    int b = i / CC, c = i % CC;
    out[(size_t)b * 197 * CC + c] = x[(size_t)b * 197 * CC + c];
}

// ---------------- copy pixel tokens, split to bf16 hi/lo ----------------
__global__ void k_copyx(const float* __restrict__ x) {
    int i = blockIdx.x * blockDim.x + threadIdx.x;
    if (i >= ROWS * (CC / 4)) return;
    int c4  = i % (CC / 4);
    int row = i / (CC / 4);
    int b = row / NPIX, p = row % NPIX;
    float4 v = *(const float4*)(x + ((size_t)b * 197 + 1 + p) * CC + c4 * 4);
    uint2 hi, lo;
    split2(v.x, v.y, hi.x, lo.x);
    split2(v.z, v.w, hi.y, lo.y);
    *(uint2*)(g_ahi + (size_t)row * CC + c4 * 4) = hi;
    *(uint2*)(g_alo + (size_t)row * CC + c4 * 4) = lo;
}

// ---------------- weight split (vectorized x4) ----------------
__global__ void k_cvt_w(const float* __restrict__ w, int total4) {
    int i = blockIdx.x * blockDim.x + threadIdx.x;
    if (i >= total4) return;
    float4 v = *(const float4*)(w + (size_t)i * 4);
    uint2 hi, lo;
    split2(v.x, v.y, hi.x, lo.x);
    split2(v.z, v.w, hi.y, lo.y);
    *(uint2*)(g_whi + (size_t)i * 4) = hi;
    *(uint2*)(g_wlo + (size_t)i * 4) = lo;
}

// ---------------- SE-scaled + BN2/hswish split (pw2 input) ----------------
__global__ void k_cvt_a_se() {
    int i = blockIdx.x * blockDim.x + threadIdx.x;
    if (i >= ROWS * (HIDN / 4)) return;
    int c4 = (i % (HIDN / 4)) * 4;
    int b  = i / (NPIX * (HIDN / 4));
    float4 v  = *(float4*)(g_h2 + (size_t)i * 4);
    float4 sc = *(float4*)(g_bnsc + c4);
    float4 sh = *(float4*)(g_bnsh + c4);
    float4 ss = *(float4*)(g_sescale + (size_t)b * HIDN + c4);
    float a0 = hsw(v.x * sc.x + sh.x) * ss.x;
    float a1 = hsw(v.y * sc.y + sh.y) * ss.y;
    float a2 = hsw(v.z * sc.z + sh.z) * ss.z;
    float a3 = hsw(v.w * sc.w + sh.w) * ss.w;
    uint2 hi, lo;
    split2(a0, a1, hi.x, lo.x);
    split2(a2, a3, hi.y, lo.y);
    *(uint2*)(g_ahi + (size_t)i * 4) = hi;
    *(uint2*)(g_alo + (size_t)i * 4) = lo;
}

// ---------------- HMMA GEMM: C[M,N] = A[M,K] @ W[N,K]^T (bf16 3-pass split) ---
// 128x128 CTA tile, BK=32, 8 warps (2x4), warp tile 64x32, 3-stage cp.async,
// fragment double-buffering across the two k-substeps.
// MODE: 0:qkv 1:xattn(+bias, +split out) 2:h1(+stats) 3:h3(+stats)
#define TS   40
#define TILE (128 * TS)
#define STG  (4 * TILE)
#define GSMEM (3 * STG * 2)        // 122880 B

template <int MODE>
__global__ __launch_bounds__(256)
void k_tc_gemm(int N, int K, const float* __restrict__ bias) {
    extern __shared__ __nv_bfloat16 smem[];
    const uint32_t sb = s2u(smem);
    const int tid = threadIdx.x, wid = tid >> 5, lane = tid & 31;
    const int nBase = blockIdx.x * 128, mBase = blockIdx.y * 128;
    const int KC = K >> 5;

    const __nv_bfloat16* Ahi = (MODE == 1) ? g_bhi : g_ahi;
    const __nv_bfloat16* Alo = (MODE == 1) ? g_blo : g_alo;
    float* Cmat = (MODE == 0) ? g_qkv : (MODE == 1) ? g_xattn : (MODE == 2) ? g_h1 : g_h3;

    __shared__ float ssum[128], ssq[128];
    if (MODE >= 2 && tid < 128) { ssum[tid] = 0.f; ssq[tid] = 0.f; }

    int cs[8], cr[8], ct[8];
#pragma unroll
    for (int j = 0; j < 8; j++) {
        int s = tid + j * 256;
        ct[j] = s >> 9;
        cr[j] = (s >> 2) & 127;
        cs[j] = s & 3;
    }

    auto issue_stage = [&](int kc, int stg) {
#pragma unroll
        for (int j = 0; j < 8; j++) {
            int t = ct[j], r = cr[j], c4 = cs[j];
            const __nv_bfloat16* src = (t == 0) ? Ahi : (t == 1) ? Alo : (t == 2) ? g_whi : g_wlo;
            int rowg = ((t < 2) ? mBase : nBase) + r;
            const __nv_bfloat16* gp = src + (size_t)rowg * K + (kc << 5) + (c4 << 3);
            uint32_t dst = sb + (uint32_t)(stg * STG + t * TILE + r * TS + (c4 << 3)) * 2;
            CPA16(dst, gp);
        }
        CPA_COMMIT();
    };

    float acc[4][4][4];
#pragma unroll
    for (int mi = 0; mi < 4; mi++)
#pragma unroll
        for (int ni = 0; ni < 4; ni++)
#pragma unroll
            for (int c = 0; c < 4; c++) acc[mi][ni][c] = 0.f;

    const int m0 = (wid >> 2) * 64;
    const int n0 = (wid & 3) * 32;
    const int arow = (lane & 15);
    const int akb  = (lane >> 4) * 8;
    const int l16  = lane & 15;
    const int brow = (l16 & 7);
    const int bkb  = (l16 >> 3) * 8;

    issue_stage(0, 0);
    if (KC > 1) issue_stage(1, 1);

    for (int kc = 0; kc < KC; kc++) {
        if (kc == KC - 1) { CPA_WAIT0(); } else { CPA_WAIT1(); }
        __syncthreads();
        if (kc + 2 < KC) issue_stage(kc + 2, (kc + 2) % 3);

        const uint32_t base = sb + (uint32_t)((kc % 3) * STG) * 2;
        const uint32_t bAh = base;
        const uint32_t bAl = base + TILE * 2;
        const uint32_t bWh = base + 2 * TILE * 2;
        const uint32_t bWl = base + 3 * TILE * 2;

        uint32_t ah[2][4][4], al[2][4][4], bh[2][4][2], bl[2][4][2];
        // load fragments for both k-substeps up-front (double-buffered)
#pragma unroll
        for (int ks = 0; ks < 2; ks++) {
            const uint32_t ak = (uint32_t)(ks * 16 + akb) * 2;
            const uint32_t bk = (uint32_t)(ks * 16 + bkb) * 2;
#pragma unroll
            for (int mi = 0; mi < 4; mi++)
                ldmA(ah[ks][mi], bAh + (uint32_t)((m0 + mi * 16 + arow) * TS) * 2 + ak);
#pragma unroll
            for (int ni = 0; ni < 4; ni++)
                ldmB(bh[ks][ni], bWh + (uint32_t)((n0 + ni * 8 + brow) * TS) * 2 + bk);
#pragma unroll
            for (int mi = 0; mi < 4; mi++)
                ldmA(al[ks][mi], bAl + (uint32_t)((m0 + mi * 16 + arow) * TS) * 2 + ak);
#pragma unroll
            for (int ni = 0; ni < 4; ni++)
                ldmB(bl[ks][ni], bWl + (uint32_t)((n0 + ni * 8 + brow) * TS) * 2 + bk);
        }
#pragma unroll
        for (int ks = 0; ks < 2; ks++) {
#pragma unroll
            for (int mi = 0; mi < 4; mi++)
#pragma unroll
                for (int ni = 0; ni < 4; ni++) mma16816(acc[mi][ni], ah[ks][mi], bh[ks][ni]);
#pragma unroll
            for (int mi = 0; mi < 4; mi++)
#pragma unroll
                for (int ni = 0; ni < 4; ni++) mma16816(acc[mi][ni], ah[ks][mi], bl[ks][ni]);
#pragma unroll
            for (int mi = 0; mi < 4; mi++)
#pragma unroll
                for (int ni = 0; ni < 4; ni++) mma16816(acc[mi][ni], al[ks][mi], bh[ks][ni]);
        }
    }

    const int gq = lane >> 2, gr = (lane & 3) * 2;
#pragma unroll
    for (int mi = 0; mi < 4; mi++) {
        int rowA = mBase + m0 + mi * 16 + gq;
#pragma unroll
        for (int ni = 0; ni < 4; ni++) {
            int col = nBase + n0 + ni * 8 + gr;
            float b0 = 0.f, b1 = 0.f;
            if (MODE == 1) { b0 = bias[col]; b1 = bias[col + 1]; }
            float v00 = acc[mi][ni][0] + b0, v01 = acc[mi][ni][1] + b1;
            float v10 = acc[mi][ni][2] + b0, v11 = acc[mi][ni][3] + b1;
            *(float2*)(Cmat + (size_t)rowA * N + col) = make_float2(v00, v01);
            *(float2*)(Cmat + (size_t)(rowA + 8) * N + col) = make_float2(v10, v11);
            if (MODE == 1) {   // also emit split for pw1's A
                uint32_t hi, lo;
                split2(v00, v01, hi, lo);
                *(uint32_t*)(g_ahi + (size_t)rowA * N + col) = hi;
                *(uint32_t*)(g_alo + (size_t)rowA * N + col) = lo;
                split2(v10, v11, hi, lo);
                *(uint32_t*)(g_ahi + (size_t)(rowA + 8) * N + col) = hi;
                *(uint32_t*)(g_alo + (size_t)(rowA + 8) * N + col) = lo;
            }
        }
    }
    if (MODE >= 2) {   // fused BN column stats
        __syncthreads();
#pragma unroll
        for (int ni = 0; ni < 4; ni++) {
            int lc = n0 + ni * 8 + gr;
            float s0 = 0.f, q0 = 0.f, s1 = 0.f, q1 = 0.f;
#pragma unroll
            for (int mi = 0; mi < 4; mi++) {
                float v00 = acc[mi][ni][0], v01 = acc[mi][ni][1];
                float v10 = acc[mi][ni][2], v11 = acc[mi][ni][3];
                s0 += v00 + v10; q0 += v00 * v00 + v10 * v10;
                s1 += v01 + v11; q1 += v01 * v01 + v11 * v11;
            }
            atomicAdd(&ssum[lc], s0);     atomicAdd(&ssq[lc], q0);
            atomicAdd(&ssum[lc + 1], s1); atomicAdd(&ssq[lc + 1], q1);
        }
        __syncthreads();
        if (tid < 128) {
            atomicAdd(&g_s1[nBase + tid], ssum[tid]);
            atomicAdd(&g_s2[nBase + tid], ssq[tid]);
        }
    }
    (void)bias;
}

// ---------------- fused window attention (register-tiled) ----------------
#define AT_ST 68
#define ATT_SMEM ((3 * NWIN * AT_ST + 50 * 50) * 4)
__global__ __launch_bounds__(256) void k_attn(const float* __restrict__ rpb) {
    extern __shared__ float asmem[];
    float* qs = asmem;
    float* ks = qs + NWIN * AT_ST;
    float* vs = ks + NWIN * AT_ST;
    float* sc = vs + NWIN * AT_ST;
    __shared__ int prow[NWIN];
    __shared__ int lab [NWIN];

    const int bw = blockIdx.x;
    const int h  = blockIdx.y;
    const int tid = threadIdx.x;
    const int b = bw >> 2, w = bw & 3;

    if (tid < NWIN) {
        int rr = (w >> 1) * 7 + tid / 7;
        int cc = (w & 1) * 7 + tid % 7;
        prow[tid] = b * NPIX + ((rr + 3) % 14) * 14 + ((cc + 3) % 14);
        lab[tid]  = reg3(rr) * 3 + reg3(cc);
    }
    __syncthreads();

    for (int idx = tid; idx < NWIN * HD; idx += 256) {
        int t = idx >> 6, d = idx & 63;
        const float* base = g_qkv + (size_t)prow[t] * (3 * CC) + h * HD + d;
        qs[t * AT_ST + d] = base[0];
        ks[t * AT_ST + d] = base[CC];
        vs[t * AT_ST + d] = base[2 * CC];
    }
    __syncthreads();

    if (tid < 169) {
        const int tq = (tid / 13) * 4, tk = (tid % 13) * 4;
        float a[4][4];
#pragma unroll
        for (int i = 0; i < 4; i++)
#pragma unroll
            for (int j = 0; j < 4; j++) a[i][j] = 0.f;
#pragma unroll
        for (int d4 = 0; d4 < 16; d4++) {
            float4 qv[4], kv[4];
#pragma unroll
            for (int j = 0; j < 4; j++) {
                qv[j] = *(float4*)&qs[min(tq + j, 48) * AT_ST + d4 * 4];
                kv[j] = *(float4*)&ks[min(tk + j, 48) * AT_ST + d4 * 4];
            }
#pragma unroll
            for (int i = 0; i < 4; i++)
#pragma unroll
                for (int j = 0; j < 4; j++)
                    a[i][j] += qv[i].x * kv[j].x + qv[i].y * kv[j].y
                             + qv[i].z * kv[j].z + qv[i].w * kv[j].w;
        }
#pragma unroll
        for (int i = 0; i < 4; i++) {
            int qi = tq + i;
            if (qi >= NWIN) break;
            int qr = qi / 7, qc = qi % 7;
#pragma unroll
            for (int j = 0; j < 4; j++) {
                int ki = tk + j;
                if (ki >= NWIN) continue;
                int kr = ki / 7, kc = ki % 7;
                float v = a[i][j] * 0.125f + rpb[((qr - kr + 6) * 13 + (qc - kc + 6)) * HH + h];
                if (lab[qi] != lab[ki]) v -= 100.f;
                sc[qi * 50 + ki] = v;
            }
        }
    }
    __syncthreads();

    if (tid < NWIN) {
        float m = -1e30f;
        for (int k = 0; k < NWIN; k++) m = fmaxf(m, sc[tid * 50 + k]);
        float sum = 0.f;
        for (int k = 0; k < NWIN; k++) {
            float e = expf(sc[tid * 50 + k] - m);
            sc[tid * 50 + k] = e; sum += e;
        }
        float inv = 1.f / sum;
        for (int k = 0; k < NWIN; k++) sc[tid * 50 + k] *= inv;
    }
    __syncthreads();

    if (tid < 200) {
        const int tq = (tid / 8) * 2, d8 = (tid % 8) * 8;
        float a0[8], a1[8];
#pragma unroll
        for (int j = 0; j < 8; j++) { a0[j] = 0.f; a1[j] = 0.f; }
        for (int k = 0; k < NWIN; k++) {
            float s0 = sc[tq * 50 + k];
            float s1 = sc[(tq + 1) * 50 + k];
            float4 va = *(float4*)&vs[k * AT_ST + d8];
            float4 vb = *(float4*)&vs[k * AT_ST + d8 + 4];
            a0[0] += s0 * va.x; a0[1] += s0 * va.y; a0[2] += s0 * va.z; a0[3] += s0 * va.w;
            a0[4] += s0 * vb.x; a0[5] += s0 * vb.y; a0[6] += s0 * vb.z; a0[7] += s0 * vb.w;
            a1[0] += s1 * va.x; a1[1] += s1 * va.y; a1[2] += s1 * va.z; a1[3] += s1 * va.w;
            a1[4] += s1 * vb.x; a1[5] += s1 * vb.y; a1[6] += s1 * vb.z; a1[7] += s1 * vb.w;
        }
#pragma unroll
        for (int r = 0; r < 2; r++) {
            int qi = tq + r;
            if (qi >= NWIN) continue;
            float* av = r ? a1 : a0;
            size_t off = (size_t)prow[qi] * CC + h * HD + d8;
#pragma unroll
            for (int j = 0; j < 4; j++) {
                uint32_t hi, lo;
                split2(av[2 * j], av[2 * j + 1], hi, lo);
                *(uint32_t*)(g_bhi + off + 2 * j) = hi;
                *(uint32_t*)(g_blo + off + 2 * j) = lo;
            }
        }
    }
}

// ---------------- BN stats ----------------
__global__ void k_zero_stats() {
    int i = blockIdx.x * blockDim.x + threadIdx.x;
    if (i < HIDN) { g_s1[i] = 0.f; g_s2[i] = 0.f; }
}
__global__ void k_colstats_h2(int N) {
    int ch = blockIdx.x * 128 + threadIdx.x;
    int r0 = blockIdx.y * 128;
    float s = 0.f, q = 0.f;
    for (int r = 0; r < 128; r++) {
        float v = g_h2[(size_t)(r0 + r) * N + ch];
        s += v; q += v * v;
    }
    atomicAdd(&g_s1[ch], s);
    atomicAdd(&g_s2[ch], q);
}
__global__ void k_bnprep(const float* __restrict__ g, const float* __restrict__ b, int N) {
    int ch = blockIdx.x * blockDim.x + threadIdx.x;
    if (ch >= N) return;
    float m   = g_s1[ch] * (1.f / ROWS);
    float var = fmaxf(g_s2[ch] * (1.f / ROWS) - m * m, 0.f);
    float sc  = g[ch] * rsqrtf(var + 1e-5f);
    g_bnsc[ch] = sc;
    g_bnsh[ch] = b[ch] - m * sc;
}

// ---------------- depthwise 3x3 with fused BN1+hswish on input ----------------
__global__ void k_dwconv(const float* __restrict__ w) {
    int i = blockIdx.x * blockDim.x + threadIdx.x;
    if (i >= ROWS * (HIDN / 4)) return;
    int c4  = i % (HIDN / 4);
    int pix = i / (HIDN / 4);
    int b = pix / NPIX, p = pix % NPIX;
    int r = p / 14, c = p % 14;

    float4 sc = *(float4*)(g_bnsc + c4 * 4);
    float4 sh = *(float4*)(g_bnsh + c4 * 4);
    float wt[4][9];
#pragma unroll
    for (int j = 0; j < 4; j++)
#pragma unroll
        for (int t = 0; t < 9; t++) wt[j][t] = w[(size_t)(c4 * 4 + j) * 9 + t];

    float acc[4] = {0.f, 0.f, 0.f, 0.f};
#pragma unroll
    for (int dr = 0; dr < 3; dr++) {
        int rr = r + dr - 1;
        if (rr < 0 || rr > 13) continue;
#pragma unroll
        for (int dc = 0; dc < 3; dc++) {
            int cc = c + dc - 1;
            if (cc < 0 || cc > 13) continue;
            float4 v = *(const float4*)(g_h1 + ((size_t)(b * NPIX + rr * 14 + cc)) * HIDN + c4 * 4);
            float t0 = hsw(v.x * sc.x + sh.x);
            float t1 = hsw(v.y * sc.y + sh.y);
            float t2 = hsw(v.z * sc.z + sh.z);
            float t3 = hsw(v.w * sc.w + sh.w);
            acc[0] += t0 * wt[0][dr * 3 + dc];
            acc[1] += t1 * wt[1][dr * 3 + dc];
            acc[2] += t2 * wt[2][dr * 3 + dc];
            acc[3] += t3 * wt[3][dr * 3 + dc];
        }
    }
    *(float4*)(g_h2 + (size_t)i * 4) = make_float4(acc[0], acc[1], acc[2], acc[3]);
}

// ---------------- SE: pool (fused BN2+hswish) + weight-stationary MLP ---------
__global__ void k_sepool() {
    int b  = blockIdx.x;
    int ch = blockIdx.y * 128 + threadIdx.x;
    float sc = g_bnsc[ch], sh = g_bnsh[ch];
    float s = 0.f;
    for (int p = 0; p < NPIX; p++)
        s += hsw(g_h2[((size_t)b * NPIX + p) * HIDN + ch] * sc + sh);
    g_semean[b * HIDN + ch] = s * (1.f / NPIX);
}
// stage1: hid[32,768] = relu(semean[32,3072] @ w1^T + b1); weights read ONCE.
__global__ __launch_bounds__(256) void k_semlp1(
    const float* __restrict__ w1, const float* __restrict__ b1)
{
    __shared__ float st[32][128];
    const int half = threadIdx.x >> 7;       // batches 0-15 / 16-31
    const int jloc = threadIdx.x & 127;
    const int j = blockIdx.x * 128 + jloc;   // output channel (768)
    float acc[16];
#pragma unroll
    for (int b = 0; b < 16; b++) acc[b] = 0.f;
    for (int k0 = 0; k0 < HIDN; k0 += 128) {
        for (int t = threadIdx.x; t < 32 * 128; t += 256) {
            int b = t >> 7, k = t & 127;
            st[b][k] = g_semean[(size_t)b * HIDN + k0 + k];
        }
        __syncthreads();
        const float* wr = w1 + (size_t)j * HIDN + k0;
#pragma unroll 4
        for (int k = 0; k < 128; k++) {
            float wv = wr[k];
#pragma unroll
            for (int b = 0; b < 16; b++) acc[b] += wv * st[half * 16 + b][k];
        }
        __syncthreads();
    }
    float bj = b1[j];
#pragma unroll
    for (int b = 0; b < 16; b++)
        g_sehid[(size_t)(half * 16 + b) * CC + j] = fmaxf(acc[b] + bj, 0.f);
}
// stage2: sescale[32,3072] = hsig(hid[32,768] @ w2^T + b2); weights read ONCE.
__global__ __launch_bounds__(256) void k_semlp2(
    const float* __restrict__ w2, const float* __restrict__ b2)
{
    __shared__ float st[32][128];
    const int half = threadIdx.x >> 7;
    const int jloc = threadIdx.x & 127;
    const int j = blockIdx.x * 128 + jloc;   // output channel (3072)
    float acc[16];
#pragma unroll
    for (int b = 0; b < 16; b++) acc[b] = 0.f;
    for (int k0 = 0; k0 < CC; k0 += 128) {
        for (int t = threadIdx.x; t < 32 * 128; t += 256) {
            int b = t >> 7, k = t & 127;
            st[b][k] = g_sehid[(size_t)b * CC + k0 + k];
        }
        __syncthreads();
        const float* wr = w2 + (size_t)j * CC + k0;
#pragma unroll 4
        for (int k = 0; k < 128; k++) {
            float wv = wr[k];
#pragma unroll
            for (int b = 0; b < 16; b++) acc[b] += wv * st[half * 16 + b][k];
        }
        __syncthreads();
    }
    float bj = b2[j];
#pragma unroll
    for (int b = 0; b < 16; b++)
        g_sescale[(size_t)(half * 16 + b) * HIDN + j] =
            fminf(fmaxf(acc[b] + bj + 3.f, 0.f), 6.f) * (1.f / 6.f);
}

// ---------------- final: bn3 + residual + write out ----------------
__global__ void k_final(const float* __restrict__ g, const float* __restrict__ bb,
                        float* __restrict__ out) {
    int i = blockIdx.x * blockDim.x + threadIdx.x;
    if (i >= ROWS * (CC / 4)) return;
    int c4  = (i % (CC / 4)) * 4;
    int pix = i / (CC / 4);
    int b = pix / NPIX, p = pix % NPIX;
    float4 hv = *(float4*)(g_h3 + (size_t)i * 4);
    float4 xv = *(float4*)(g_xattn + (size_t)i * 4);
    float h[4] = { hv.x, hv.y, hv.z, hv.w };
    float x[4] = { xv.x, xv.y, xv.z, xv.w };
#pragma unroll
    for (int j = 0; j < 4; j++) {
        int ch = c4 + j;
        float m   = g_s1[ch] * (1.f / ROWS);
        float var = fmaxf(g_s2[ch] * (1.f / ROWS) - m * m, 0.f);
        x[j] += (h[j] - m) * rsqrtf(var + 1e-5f) * g[ch] + bb[ch];
    }
    float* dst = out + ((size_t)b * 197 + 1 + p) * CC + c4;
    *(float4*)dst = make_float4(x[0], x[1], x[2], x[3]);
}

// ---------------- launch ----------------
extern "C" void kernel_launch(void* const* d_in, const int* in_sizes, int n_in,
                              void* d_out, int out_size) {
    int idx[18];
    for (int i = 0; i < 18; i++) idx[i] = i;
    const int X_ELEMS = BB * 197 * CC;
    if (n_in == 18 && in_sizes[0] != X_ELEMS && in_sizes[17] == X_ELEMS) {
        const int m[18] = {17, 16, 15, 0, 10, 8, 2, 1, 7, 4, 3, 13, 11, 14, 12, 9, 6, 5};
        for (int i = 0; i < 18; i++) idx[i] = m[i];
    }

    const float* x      = (const float*)d_in[idx[0]];
    const float* w_qkv  = (const float*)d_in[idx[1]];
    const float* w_proj = (const float*)d_in[idx[2]];
    const float* b_proj = (const float*)d_in[idx[3]];
    const float* rpb    = (const float*)d_in[idx[4]];
    const float* pw1_w  = (const float*)d_in[idx[5]];
    const float* bn1_g  = (const float*)d_in[idx[6]];
    const float* bn1_b  = (const float*)d_in[idx[7]];
    const float* dw_w   = (const float*)d_in[idx[8]];
    const float* bn2_g  = (const float*)d_in[idx[9]];
    const float* bn2_b  = (const float*)d_in[idx[10]];
    const float* se_w1  = (const float*)d_in[idx[11]];
    const float* se_b1  = (const float*)d_in[idx[12]];
    const float* se_w2  = (const float*)d_in[idx[13]];
    const float* se_b2  = (const float*)d_in[idx[14]];
    const float* pw2_w  = (const float*)d_in[idx[15]];
    const float* bn3_g  = (const float*)d_in[idx[16]];
    const float* bn3_b  = (const float*)d_in[idx[17]];
    float* out = (float*)d_out;

    cudaFuncSetAttribute(k_tc_gemm<0>, cudaFuncAttributeMaxDynamicSharedMemorySize, GSMEM);
    cudaFuncSetAttribute(k_tc_gemm<1>, cudaFuncAttributeMaxDynamicSharedMemorySize, GSMEM);
    cudaFuncSetAttribute(k_tc_gemm<2>, cudaFuncAttributeMaxDynamicSharedMemorySize, GSMEM);
    cudaFuncSetAttribute(k_tc_gemm<3>, cudaFuncAttributeMaxDynamicSharedMemorySize, GSMEM);
    cudaFuncSetAttribute(k_attn, cudaFuncAttributeMaxDynamicSharedMemorySize, ATT_SMEM);

    k_cls<<<(BB * CC + 255) / 256, 256>>>(x, out);
    k_copyx<<<(ROWS * (CC / 4) + 255) / 256, 256>>>(x);

    // QKV
    k_cvt_w<<<(3 * CC * CC / 4 + 255) / 256, 256>>>(w_qkv, 3 * CC * CC / 4);
    k_tc_gemm<0><<<dim3(3 * CC / 128, ROWS / 128), 256, GSMEM>>>(3 * CC, CC, nullptr);

    k_attn<<<dim3(BB * 4, HH), 256, ATT_SMEM>>>(rpb);

    // proj (writes fp32 xattn + bf16 split for pw1)
    k_cvt_w<<<(CC * CC / 4 + 255) / 256, 256>>>(w_proj, CC * CC / 4);
    k_tc_gemm<1><<<dim3(CC / 128, ROWS / 128), 256, GSMEM>>>(CC, CC, b_proj);

    // pw1 (+fused h1 stats)
    k_cvt_w<<<(HIDN * CC / 4 + 255) / 256, 256>>>(pw1_w, HIDN * CC / 4);
    k_zero_stats<<<(HIDN + 255) / 256, 256>>>();
    k_tc_gemm<2><<<dim3(HIDN / 128, ROWS / 128), 256, GSMEM>>>(HIDN, CC, nullptr);
    k_bnprep<<<(HIDN + 255) / 256, 256>>>(bn1_g, bn1_b, HIDN);

    k_dwconv<<<(ROWS * (HIDN / 4) + 255) / 256, 256>>>(dw_w);

    // bn2 stats -> params
    k_zero_stats<<<(HIDN + 255) / 256, 256>>>();
    k_colstats_h2<<<dim3(HIDN / 128, ROWS / 128), 128>>>(HIDN);
    k_bnprep<<<(HIDN + 255) / 256, 256>>>(bn2_g, bn2_b, HIDN);

    k_sepool<<<dim3(BB, HIDN / 128), 128>>>();
    k_semlp1<<<CC / 128, 256>>>(se_w1, se_b1);
    k_semlp2<<<HIDN / 128, 256>>>(se_w2, se_b2);

    // pw2 (+fused h3 stats)
    k_cvt_a_se<<<(ROWS * (HIDN / 4) + 255) / 256, 256>>>();
    k_cvt_w<<<(CC * HIDN / 4 + 255) / 256, 256>>>(pw2_w, CC * HIDN / 4);
    k_zero_stats<<<(HIDN + 255) / 256, 256>>>();
    k_tc_gemm<3><<<dim3(CC / 128, ROWS / 128), 256, GSMEM>>>(CC, HIDN, nullptr);

    k_final<<<(ROWS * (CC / 4) + 255) / 256, 256>>>(bn3_g, bn3_b, out);
    (void)in_sizes; (void)n_in; (void)out_size;
}

// round 16
// speedup vs baseline: 1.0972x; 1.0972x over previous
#include <cuda_runtime.h>
#include <cuda_bf16.h>
#include <cstdint>

// ---------------- problem constants ----------------
#define BB    32
#define PP    14
#define CC    768
#define HH    12
#define HD    64
#define HIDN  3072
#define NWIN  49
#define NPIX  196
#define ROWS  6272         // 32*196

// ---------------- scratch ----------------
__device__ float g_qkv  [(size_t)ROWS * 3 * CC];
__device__ float g_xattn[(size_t)ROWS * CC];
__device__ float g_h1   [(size_t)ROWS * HIDN];
__device__ float g_h2   [(size_t)ROWS * HIDN];
__device__ float g_h3   [(size_t)ROWS * CC];
__device__ float g_s1   [HIDN];
__device__ float g_s2   [HIDN];
__device__ float g_semean [BB * HIDN];
__device__ float g_sehid  [BB * CC];
__device__ float g_sescale[BB * HIDN];
__device__ float g_bnsc [HIDN];
__device__ float g_bnsh [HIDN];
// bf16 split buffers
__device__ __nv_bfloat16 g_ahi[(size_t)ROWS * HIDN];
__device__ __nv_bfloat16 g_alo[(size_t)ROWS * HIDN];
__device__ __nv_bfloat16 g_bhi[(size_t)ROWS * CC];
__device__ __nv_bfloat16 g_blo[(size_t)ROWS * CC];
__device__ __nv_bfloat16 g_whi[(size_t)HIDN * CC];
__device__ __nv_bfloat16 g_wlo[(size_t)HIDN * CC];

__device__ __forceinline__ int reg3(int r) { return r < 7 ? 0 : (r < 11 ? 1 : 2); }
__device__ __forceinline__ float hsw(float x) { return x * __saturatef((x + 3.f) * (1.f / 6.f)); }
__device__ __forceinline__ void split2(float a, float b, uint32_t& hi, uint32_t& lo) {
    __nv_bfloat16 ha = __float2bfloat16(a), hb = __float2bfloat16(b);
    __nv_bfloat16 la = __float2bfloat16(a - __bfloat162float(ha));
    __nv_bfloat16 lb = __float2bfloat16(b - __bfloat162float(hb));
    __nv_bfloat162 H = __halves2bfloat162(ha, hb), L = __halves2bfloat162(la, lb);
    hi = *(uint32_t*)&H; lo = *(uint32_t*)&L;
}
__device__ __forceinline__ uint32_t s2u(const void* p) {
    uint32_t a;
    asm("{ .reg .u64 t; cvta.to.shared.u64 t, %1; cvt.u32.u64 %0, t; }" : "=r"(a) : "l"(p));
    return a;
}
#define CPA16(dst, src) asm volatile("cp.async.cg.shared.global [%0], [%1], 16;" :: "r"(dst), "l"(src) : "memory")
#define CPA_COMMIT()    asm volatile("cp.async.commit_group;" ::: "memory")
#define CPA_WAIT1()     asm volatile("cp.async.wait_group 1;" ::: "memory")
#define CPA_WAIT0()     asm volatile("cp.async.wait_group 0;" ::: "memory")

__device__ __forceinline__ void ldmA(uint32_t* r, uint32_t addr) {
    asm volatile("ldmatrix.sync.aligned.m8n8.x4.shared.b16 {%0,%1,%2,%3}, [%4];"
                 : "=r"(r[0]), "=r"(r[1]), "=r"(r[2]), "=r"(r[3]) : "r"(addr));
}
__device__ __forceinline__ void ldmB(uint32_t* r, uint32_t addr) {
    asm volatile("ldmatrix.sync.aligned.m8n8.x2.shared.b16 {%0,%1}, [%2];"
                 : "=r"(r[0]), "=r"(r[1]) : "r"(addr));
}
__device__ __forceinline__ void mma16816(float* c, const uint32_t* a, const uint32_t* b) {
    asm volatile("mma.sync.aligned.m16n8k16.row.col.f32.bf16.bf16.f32 "
                 "{%0,%1,%2,%3}, {%4,%5,%6,%7}, {%8,%9}, {%0,%1,%2,%3};"
                 : "+f"(c[0]), "+f"(c[1]), "+f"(c[2]), "+f"(c[3])
                 : "r"(a[0]), "r"(a[1]), "r"(a[2]), "r"(a[3]), "r"(b[0]), "r"(b[1]));
}

// ---------------- cls passthrough ----------------
__global__ void k_cls(const float* __restrict__ x, float* __restrict__ out) {
    int i = blockIdx.x * blockDim.x + threadIdx.x;
    if (i >= BB * CC) return;
    int b = i / CC, c = i % CC;
    out[(size_t)b * 197 * CC + c] = x[(size_t)b * 197 * CC + c];
}

// ---------------- copy pixel tokens, split to bf16 hi/lo ----------------
__global__ void k_copyx(const float* __restrict__ x) {
    int i = blockIdx.x * blockDim.x + threadIdx.x;
    if (i >= ROWS * (CC / 4)) return;
    int c4  = i % (CC / 4);
    int row = i / (CC / 4);
    int b = row / NPIX, p = row % NPIX;
    float4 v = *(const float4*)(x + ((size_t)b * 197 + 1 + p) * CC + c4 * 4);
    uint2 hi, lo;
    split2(v.x, v.y, hi.x, lo.x);
    split2(v.z, v.w, hi.y, lo.y);
    *(uint2*)(g_ahi + (size_t)row * CC + c4 * 4) = hi;
    *(uint2*)(g_alo + (size_t)row * CC + c4 * 4) = lo;
}

// ---------------- weight split (vectorized x4) ----------------
__global__ void k_cvt_w(const float* __restrict__ w, int total4) {
    int i = blockIdx.x * blockDim.x + threadIdx.x;
    if (i >= total4) return;
    float4 v = *(const float4*)(w + (size_t)i * 4);
    uint2 hi, lo;
    split2(v.x, v.y, hi.x, lo.x);
    split2(v.z, v.w, hi.y, lo.y);
    *(uint2*)(g_whi + (size_t)i * 4) = hi;
    *(uint2*)(g_wlo + (size_t)i * 4) = lo;
}

// ---------------- SE-scaled + BN2/hswish split (pw2 input) ----------------
__global__ void k_cvt_a_se() {
    int i = blockIdx.x * blockDim.x + threadIdx.x;
    if (i >= ROWS * (HIDN / 4)) return;
    int c4 = (i % (HIDN / 4)) * 4;
    int b  = i / (NPIX * (HIDN / 4));
    float4 v  = *(float4*)(g_h2 + (size_t)i * 4);
    float4 sc = *(float4*)(g_bnsc + c4);
    float4 sh = *(float4*)(g_bnsh + c4);
    float4 ss = *(float4*)(g_sescale + (size_t)b * HIDN + c4);
    float a0 = hsw(v.x * sc.x + sh.x) * ss.x;
    float a1 = hsw(v.y * sc.y + sh.y) * ss.y;
    float a2 = hsw(v.z * sc.z + sh.z) * ss.z;
    float a3 = hsw(v.w * sc.w + sh.w) * ss.w;
    uint2 hi, lo;
    split2(a0, a1, hi.x, lo.x);
    split2(a2, a3, hi.y, lo.y);
    *(uint2*)(g_ahi + (size_t)i * 4) = hi;
    *(uint2*)(g_alo + (size_t)i * 4) = lo;
}

// ---------------- HMMA GEMM: C[M,N] = A[M,K] @ W[N,K]^T (bf16 3-pass split) ---
// 128x128 CTA tile, BK=32, 8 warps (2x4), warp tile 64x32.
// 2-stage cp.async pipeline, 80KB smem -> 2 CTAs/SM (16 warps/SM).
// MODE: 0:qkv 1:xattn(+bias, +split out) 2:h1(+stats) 3:h3(+stats)
#define TS   40
#define TILE (128 * TS)
#define STG  (4 * TILE)
#define GSMEM (2 * STG * 2)        // 81920 B

template <int MODE>
__global__ __launch_bounds__(256, 2)
void k_tc_gemm(int N, int K, const float* __restrict__ bias) {
    extern __shared__ __nv_bfloat16 smem[];
    const uint32_t sb = s2u(smem);
    const int tid = threadIdx.x, wid = tid >> 5, lane = tid & 31;
    const int nBase = blockIdx.x * 128, mBase = blockIdx.y * 128;
    const int KC = K >> 5;

    const __nv_bfloat16* Ahi = (MODE == 1) ? g_bhi : g_ahi;
    const __nv_bfloat16* Alo = (MODE == 1) ? g_blo : g_alo;
    float* Cmat = (MODE == 0) ? g_qkv : (MODE == 1) ? g_xattn : (MODE == 2) ? g_h1 : g_h3;

    __shared__ float ssum[128], ssq[128];
    if (MODE >= 2 && tid < 128) { ssum[tid] = 0.f; ssq[tid] = 0.f; }

    int cs[8], cr[8], ct[8];
#pragma unroll
    for (int j = 0; j < 8; j++) {
        int s = tid + j * 256;
        ct[j] = s >> 9;
        cr[j] = (s >> 2) & 127;
        cs[j] = s & 3;
    }

    auto issue_stage = [&](int kc, int stg) {
#pragma unroll
        for (int j = 0; j < 8; j++) {
            int t = ct[j], r = cr[j], c4 = cs[j];
            const __nv_bfloat16* src = (t == 0) ? Ahi : (t == 1) ? Alo : (t == 2) ? g_whi : g_wlo;
            int rowg = ((t < 2) ? mBase : nBase) + r;
            const __nv_bfloat16* gp = src + (size_t)rowg * K + (kc << 5) + (c4 << 3);
            uint32_t dst = sb + (uint32_t)(stg * STG + t * TILE + r * TS + (c4 << 3)) * 2;
            CPA16(dst, gp);
        }
        CPA_COMMIT();
    };

    float acc[4][4][4];
#pragma unroll
    for (int mi = 0; mi < 4; mi++)
#pragma unroll
        for (int ni = 0; ni < 4; ni++)
#pragma unroll
            for (int c = 0; c < 4; c++) acc[mi][ni][c] = 0.f;

    const int m0 = (wid >> 2) * 64;
    const int n0 = (wid & 3) * 32;
    const int arow = (lane & 15);
    const int akb  = (lane >> 4) * 8;
    const int l16  = lane & 15;
    const int brow = (l16 & 7);
    const int bkb  = (l16 >> 3) * 8;

    issue_stage(0, 0);

    for (int kc = 0; kc < KC; kc++) {
        if (kc + 1 < KC) { issue_stage(kc + 1, (kc + 1) & 1); CPA_WAIT1(); }
        else             { CPA_WAIT0(); }
        __syncthreads();

        const uint32_t base = sb + (uint32_t)((kc & 1) * STG) * 2;
        const uint32_t bAh = base;
        const uint32_t bAl = base + TILE * 2;
        const uint32_t bWh = base + 2 * TILE * 2;
        const uint32_t bWl = base + 3 * TILE * 2;

#pragma unroll
        for (int ks = 0; ks < 2; ks++) {
            const uint32_t ak = (uint32_t)(ks * 16 + akb) * 2;
            const uint32_t bk = (uint32_t)(ks * 16 + bkb) * 2;
            uint32_t ah[4][4], al[4][4], bh[4][2], bl[4][2];
#pragma unroll
            for (int mi = 0; mi < 4; mi++)
                ldmA(ah[mi], bAh + (uint32_t)((m0 + mi * 16 + arow) * TS) * 2 + ak);
#pragma unroll
            for (int mi = 0; mi < 4; mi++)
                ldmA(al[mi], bAl + (uint32_t)((m0 + mi * 16 + arow) * TS) * 2 + ak);
#pragma unroll
            for (int ni = 0; ni < 4; ni++)
                ldmB(bh[ni], bWh + (uint32_t)((n0 + ni * 8 + brow) * TS) * 2 + bk);
#pragma unroll
            for (int ni = 0; ni < 4; ni++)
                ldmB(bl[ni], bWl + (uint32_t)((n0 + ni * 8 + brow) * TS) * 2 + bk);
#pragma unroll
            for (int mi = 0; mi < 4; mi++)
#pragma unroll
                for (int ni = 0; ni < 4; ni++) mma16816(acc[mi][ni], ah[mi], bh[ni]);
#pragma unroll
            for (int mi = 0; mi < 4; mi++)
#pragma unroll
                for (int ni = 0; ni < 4; ni++) mma16816(acc[mi][ni], ah[mi], bl[ni]);
#pragma unroll
            for (int mi = 0; mi < 4; mi++)
#pragma unroll
                for (int ni = 0; ni < 4; ni++) mma16816(acc[mi][ni], al[mi], bh[ni]);
        }
        __syncthreads();   // protect this stage's buffer before it is re-issued
    }

    const int gq = lane >> 2, gr = (lane & 3) * 2;
#pragma unroll
    for (int mi = 0; mi < 4; mi++) {
        int rowA = mBase + m0 + mi * 16 + gq;
#pragma unroll
        for (int ni = 0; ni < 4; ni++) {
            int col = nBase + n0 + ni * 8 + gr;
            float b0 = 0.f, b1 = 0.f;
            if (MODE == 1) { b0 = bias[col]; b1 = bias[col + 1]; }
            float v00 = acc[mi][ni][0] + b0, v01 = acc[mi][ni][1] + b1;
            float v10 = acc[mi][ni][2] + b0, v11 = acc[mi][ni][3] + b1;
            *(float2*)(Cmat + (size_t)rowA * N + col) = make_float2(v00, v01);
            *(float2*)(Cmat + (size_t)(rowA + 8) * N + col) = make_float2(v10, v11);
            if (MODE == 1) {
                uint32_t hi, lo;
                split2(v00, v01, hi, lo);
                *(uint32_t*)(g_ahi + (size_t)rowA * N + col) = hi;
                *(uint32_t*)(g_alo + (size_t)rowA * N + col) = lo;
                split2(v10, v11, hi, lo);
                *(uint32_t*)(g_ahi + (size_t)(rowA + 8) * N + col) = hi;
                *(uint32_t*)(g_alo + (size_t)(rowA + 8) * N + col) = lo;
            }
        }
    }
    if (MODE >= 2) {   // fused BN column stats
        __syncthreads();
#pragma unroll
        for (int ni = 0; ni < 4; ni++) {
            int lc = n0 + ni * 8 + gr;
            float s0 = 0.f, q0 = 0.f, s1 = 0.f, q1 = 0.f;
#pragma unroll
            for (int mi = 0; mi < 4; mi++) {
                float v00 = acc[mi][ni][0], v01 = acc[mi][ni][1];
                float v10 = acc[mi][ni][2], v11 = acc[mi][ni][3];
                s0 += v00 + v10; q0 += v00 * v00 + v10 * v10;
                s1 += v01 + v11; q1 += v01 * v01 + v11 * v11;
            }
            atomicAdd(&ssum[lc], s0);     atomicAdd(&ssq[lc], q0);
            atomicAdd(&ssum[lc + 1], s1); atomicAdd(&ssq[lc + 1], q1);
        }
        __syncthreads();
        if (tid < 128) {
            atomicAdd(&g_s1[nBase + tid], ssum[tid]);
            atomicAdd(&g_s2[nBase + tid], ssq[tid]);
        }
    }
    (void)bias;
}

// ---------------- fused window attention (register-tiled) ----------------
#define AT_ST 68
#define ATT_SMEM ((3 * NWIN * AT_ST + 50 * 50) * 4)
__global__ __launch_bounds__(256) void k_attn(const float* __restrict__ rpb) {
    extern __shared__ float asmem[];
    float* qs = asmem;
    float* ks = qs + NWIN * AT_ST;
    float* vs = ks + NWIN * AT_ST;
    float* sc = vs + NWIN * AT_ST;
    __shared__ int prow[NWIN];
    __shared__ int lab [NWIN];

    const int bw = blockIdx.x;
    const int h  = blockIdx.y;
    const int tid = threadIdx.x;
    const int b = bw >> 2, w = bw & 3;

    if (tid < NWIN) {
        int rr = (w >> 1) * 7 + tid / 7;
        int cc = (w & 1) * 7 + tid % 7;
        prow[tid] = b * NPIX + ((rr + 3) % 14) * 14 + ((cc + 3) % 14);
        lab[tid]  = reg3(rr) * 3 + reg3(cc);
    }
    __syncthreads();

    for (int idx = tid; idx < NWIN * HD; idx += 256) {
        int t = idx >> 6, d = idx & 63;
        const float* base = g_qkv + (size_t)prow[t] * (3 * CC) + h * HD + d;
        qs[t * AT_ST + d] = base[0];
        ks[t * AT_ST + d] = base[CC];
        vs[t * AT_ST + d] = base[2 * CC];
    }
    __syncthreads();

    if (tid < 169) {
        const int tq = (tid / 13) * 4, tk = (tid % 13) * 4;
        float a[4][4];
#pragma unroll
        for (int i = 0; i < 4; i++)
#pragma unroll
            for (int j = 0; j < 4; j++) a[i][j] = 0.f;
#pragma unroll
        for (int d4 = 0; d4 < 16; d4++) {
            float4 qv[4], kv[4];
#pragma unroll
            for (int j = 0; j < 4; j++) {
                qv[j] = *(float4*)&qs[min(tq + j, 48) * AT_ST + d4 * 4];
                kv[j] = *(float4*)&ks[min(tk + j, 48) * AT_ST + d4 * 4];
            }
#pragma unroll
            for (int i = 0; i < 4; i++)
#pragma unroll
                for (int j = 0; j < 4; j++)
                    a[i][j] += qv[i].x * kv[j].x + qv[i].y * kv[j].y
                             + qv[i].z * kv[j].z + qv[i].w * kv[j].w;
        }
#pragma unroll
        for (int i = 0; i < 4; i++) {
            int qi = tq + i;
            if (qi >= NWIN) break;
            int qr = qi / 7, qc = qi % 7;
#pragma unroll
            for (int j = 0; j < 4; j++) {
                int ki = tk + j;
                if (ki >= NWIN) continue;
                int kr = ki / 7, kc = ki % 7;
                float v = a[i][j] * 0.125f + rpb[((qr - kr + 6) * 13 + (qc - kc + 6)) * HH + h];
                if (lab[qi] != lab[ki]) v -= 100.f;
                sc[qi * 50 + ki] = v;
            }
        }
    }
    __syncthreads();

    if (tid < NWIN) {
        float m = -1e30f;
        for (int k = 0; k < NWIN; k++) m = fmaxf(m, sc[tid * 50 + k]);
        float sum = 0.f;
        for (int k = 0; k < NWIN; k++) {
            float e = expf(sc[tid * 50 + k] - m);
            sc[tid * 50 + k] = e; sum += e;
        }
        float inv = 1.f / sum;
        for (int k = 0; k < NWIN; k++) sc[tid * 50 + k] *= inv;
    }
    __syncthreads();

    if (tid < 200) {
        const int tq = (tid / 8) * 2, d8 = (tid % 8) * 8;
        float a0[8], a1[8];
#pragma unroll
        for (int j = 0; j < 8; j++) { a0[j] = 0.f; a1[j] = 0.f; }
        for (int k = 0; k < NWIN; k++) {
            float s0 = sc[tq * 50 + k];
            float s1 = sc[(tq + 1) * 50 + k];
            float4 va = *(float4*)&vs[k * AT_ST + d8];
            float4 vb = *(float4*)&vs[k * AT_ST + d8 + 4];
            a0[0] += s0 * va.x; a0[1] += s0 * va.y; a0[2] += s0 * va.z; a0[3] += s0 * va.w;
            a0[4] += s0 * vb.x; a0[5] += s0 * vb.y; a0[6] += s0 * vb.z; a0[7] += s0 * vb.w;
            a1[0] += s1 * va.x; a1[1] += s1 * va.y; a1[2] += s1 * va.z; a1[3] += s1 * va.w;
            a1[4] += s1 * vb.x; a1[5] += s1 * vb.y; a1[6] += s1 * vb.z; a1[7] += s1 * vb.w;
        }
#pragma unroll
        for (int r = 0; r < 2; r++) {
            int qi = tq + r;
            if (qi >= NWIN) continue;
            float* av = r ? a1 : a0;
            size_t off = (size_t)prow[qi] * CC + h * HD + d8;
#pragma unroll
            for (int j = 0; j < 4; j++) {
                uint32_t hi, lo;
                split2(av[2 * j], av[2 * j + 1], hi, lo);
                *(uint32_t*)(g_bhi + off + 2 * j) = hi;
                *(uint32_t*)(g_blo + off + 2 * j) = lo;
            }
        }
    }
}

// ---------------- BN stats ----------------
__global__ void k_zero_stats() {
    int i = blockIdx.x * blockDim.x + threadIdx.x;
    if (i < HIDN) { g_s1[i] = 0.f; g_s2[i] = 0.f; }
}
__global__ void k_colstats_h2(int N) {
    int ch = blockIdx.x * 128 + threadIdx.x;
    int r0 = blockIdx.y * 128;
    float s = 0.f, q = 0.f;
    for (int r = 0; r < 128; r++) {
        float v = g_h2[(size_t)(r0 + r) * N + ch];
        s += v; q += v * v;
    }
    atomicAdd(&g_s1[ch], s);
    atomicAdd(&g_s2[ch], q);
}
__global__ void k_bnprep(const float* __restrict__ g, const float* __restrict__ b, int N) {
    int ch = blockIdx.x * blockDim.x + threadIdx.x;
    if (ch >= N) return;
    float m   = g_s1[ch] * (1.f / ROWS);
    float var = fmaxf(g_s2[ch] * (1.f / ROWS) - m * m, 0.f);
    float sc  = g[ch] * rsqrtf(var + 1e-5f);
    g_bnsc[ch] = sc;
    g_bnsh[ch] = b[ch] - m * sc;
}

// ---------------- depthwise 3x3 with fused BN1+hswish on input ----------------
__global__ void k_dwconv(const float* __restrict__ w) {
    int i = blockIdx.x * blockDim.x + threadIdx.x;
    if (i >= ROWS * (HIDN / 4)) return;
    int c4  = i % (HIDN / 4);
    int pix = i / (HIDN / 4);
    int b = pix / NPIX, p = pix % NPIX;
    int r = p / 14, c = p % 14;

    float4 sc = *(float4*)(g_bnsc + c4 * 4);
    float4 sh = *(float4*)(g_bnsh + c4 * 4);
    float wt[4][9];
#pragma unroll
    for (int j = 0; j < 4; j++)
#pragma unroll
        for (int t = 0; t < 9; t++) wt[j][t] = w[(size_t)(c4 * 4 + j) * 9 + t];

    float acc[4] = {0.f, 0.f, 0.f, 0.f};
#pragma unroll
    for (int dr = 0; dr < 3; dr++) {
        int rr = r + dr - 1;
        if (rr < 0 || rr > 13) continue;
#pragma unroll
        for (int dc = 0; dc < 3; dc++) {
            int cc = c + dc - 1;
            if (cc < 0 || cc > 13) continue;
            float4 v = *(const float4*)(g_h1 + ((size_t)(b * NPIX + rr * 14 + cc)) * HIDN + c4 * 4);
            float t0 = hsw(v.x * sc.x + sh.x);
            float t1 = hsw(v.y * sc.y + sh.y);
            float t2 = hsw(v.z * sc.z + sh.z);
            float t3 = hsw(v.w * sc.w + sh.w);
            acc[0] += t0 * wt[0][dr * 3 + dc];
            acc[1] += t1 * wt[1][dr * 3 + dc];
            acc[2] += t2 * wt[2][dr * 3 + dc];
            acc[3] += t3 * wt[3][dr * 3 + dc];
        }
    }
    *(float4*)(g_h2 + (size_t)i * 4) = make_float4(acc[0], acc[1], acc[2], acc[3]);
}

// ---------------- SE: pool (fused BN2+hswish) + weight-stationary MLP ---------
__global__ void k_sepool() {
    int b  = blockIdx.x;
    int ch = blockIdx.y * 128 + threadIdx.x;
    float sc = g_bnsc[ch], sh = g_bnsh[ch];
    float s = 0.f;
    for (int p = 0; p < NPIX; p++)
        s += hsw(g_h2[((size_t)b * NPIX + p) * HIDN + ch] * sc + sh);
    g_semean[b * HIDN + ch] = s * (1.f / NPIX);
}
__global__ __launch_bounds__(256) void k_semlp1(
    const float* __restrict__ w1, const float* __restrict__ b1)
{
    __shared__ float st[32][128];
    const int half = threadIdx.x >> 7;
    const int jloc = threadIdx.x & 127;
    const int j = blockIdx.x * 128 + jloc;
    float acc[16];
#pragma unroll
    for (int b = 0; b < 16; b++) acc[b] = 0.f;
    for (int k0 = 0; k0 < HIDN; k0 += 128) {
        for (int t = threadIdx.x; t < 32 * 128; t += 256) {
            int b = t >> 7, k = t & 127;
            st[b][k] = g_semean[(size_t)b * HIDN + k0 + k];
        }
        __syncthreads();
        const float* wr = w1 + (size_t)j * HIDN + k0;
#pragma unroll 4
        for (int k = 0; k < 128; k++) {
            float wv = wr[k];
#pragma unroll
            for (int b = 0; b < 16; b++) acc[b] += wv * st[half * 16 + b][k];
        }
        __syncthreads();
    }
    float bj = b1[j];
#pragma unroll
    for (int b = 0; b < 16; b++)
        g_sehid[(size_t)(half * 16 + b) * CC + j] = fmaxf(acc[b] + bj, 0.f);
}
__global__ __launch_bounds__(256) void k_semlp2(
    const float* __restrict__ w2, const float* __restrict__ b2)
{
    __shared__ float st[32][128];
    const int half = threadIdx.x >> 7;
    const int jloc = threadIdx.x & 127;
    const int j = blockIdx.x * 128 + jloc;
    float acc[16];
#pragma unroll
    for (int b = 0; b < 16; b++) acc[b] = 0.f;
    for (int k0 = 0; k0 < CC; k0 += 128) {
        for (int t = threadIdx.x; t < 32 * 128; t += 256) {
            int b = t >> 7, k = t & 127;
            st[b][k] = g_sehid[(size_t)b * CC + k0 + k];
        }
        __syncthreads();
        const float* wr = w2 + (size_t)j * CC + k0;
#pragma unroll 4
        for (int k = 0; k < 128; k++) {
            float wv = wr[k];
#pragma unroll
            for (int b = 0; b < 16; b++) acc[b] += wv * st[half * 16 + b][k];
        }
        __syncthreads();
    }
    float bj = b2[j];
#pragma unroll
    for (int b = 0; b < 16; b++)
        g_sescale[(size_t)(half * 16 + b) * HIDN + j] =
            fminf(fmaxf(acc[b] + bj + 3.f, 0.f), 6.f) * (1.f / 6.f);
}

// ---------------- final: bn3 + residual + write out ----------------
__global__ void k_final(const float* __restrict__ g, const float* __restrict__ bb,
                        float* __restrict__ out) {
    int i = blockIdx.x * blockDim.x + threadIdx.x;
    if (i >= ROWS * (CC / 4)) return;
    int c4  = (i % (CC / 4)) * 4;
    int pix = i / (CC / 4);
    int b = pix / NPIX, p = pix % NPIX;
    float4 hv = *(float4*)(g_h3 + (size_t)i * 4);
    float4 xv = *(float4*)(g_xattn + (size_t)i * 4);
    float h[4] = { hv.x, hv.y, hv.z, hv.w };
    float x[4] = { xv.x, xv.y, xv.z, xv.w };
#pragma unroll
    for (int j = 0; j < 4; j++) {
        int ch = c4 + j;
        float m   = g_s1[ch] * (1.f / ROWS);
        float var = fmaxf(g_s2[ch] * (1.f / ROWS) - m * m, 0.f);
        x[j] += (h[j] - m) * rsqrtf(var + 1e-5f) * g[ch] + bb[ch];
    }
    float* dst = out + ((size_t)b * 197 + 1 + p) * CC + c4;
    *(float4*)dst = make_float4(x[0], x[1], x[2], x[3]);
}

// ---------------- launch ----------------
extern "C" void kernel_launch(void* const* d_in, const int* in_sizes, int n_in,
                              void* d_out, int out_size) {
    int idx[18];
    for (int i = 0; i < 18; i++) idx[i] = i;
    const int X_ELEMS = BB * 197 * CC;
    if (n_in == 18 && in_sizes[0] != X_ELEMS && in_sizes[17] == X_ELEMS) {
        const int m[18] = {17, 16, 15, 0, 10, 8, 2, 1, 7, 4, 3, 13, 11, 14, 12, 9, 6, 5};
        for (int i = 0; i < 18; i++) idx[i] = m[i];
    }

    const float* x      = (const float*)d_in[idx[0]];
    const float* w_qkv  = (const float*)d_in[idx[1]];
    const float* w_proj = (const float*)d_in[idx[2]];
    const float* b_proj = (const float*)d_in[idx[3]];
    const float* rpb    = (const float*)d_in[idx[4]];
    const float* pw1_w  = (const float*)d_in[idx[5]];
    const float* bn1_g  = (const float*)d_in[idx[6]];
    const float* bn1_b  = (const float*)d_in[idx[7]];
    const float* dw_w   = (const float*)d_in[idx[8]];
    const float* bn2_g  = (const float*)d_in[idx[9]];
    const float* bn2_b  = (const float*)d_in[idx[10]];
    const float* se_w1  = (const float*)d_in[idx[11]];
    const float* se_b1  = (const float*)d_in[idx[12]];
    const float* se_w2  = (const float*)d_in[idx[13]];
    const float* se_b2  = (const float*)d_in[idx[14]];
    const float* pw2_w  = (const float*)d_in[idx[15]];
    const float* bn3_g  = (const float*)d_in[idx[16]];
    const float* bn3_b  = (const float*)d_in[idx[17]];
    float* out = (float*)d_out;

    cudaFuncSetAttribute(k_tc_gemm<0>, cudaFuncAttributeMaxDynamicSharedMemorySize, GSMEM);
    cudaFuncSetAttribute(k_tc_gemm<1>, cudaFuncAttributeMaxDynamicSharedMemorySize, GSMEM);
    cudaFuncSetAttribute(k_tc_gemm<2>, cudaFuncAttributeMaxDynamicSharedMemorySize, GSMEM);
    cudaFuncSetAttribute(k_tc_gemm<3>, cudaFuncAttributeMaxDynamicSharedMemorySize, GSMEM);
    cudaFuncSetAttribute(k_attn, cudaFuncAttributeMaxDynamicSharedMemorySize, ATT_SMEM);

    k_cls<<<(BB * CC + 255) / 256, 256>>>(x, out);
    k_copyx<<<(ROWS * (CC / 4) + 255) / 256, 256>>>(x);

    // QKV
    k_cvt_w<<<(3 * CC * CC / 4 + 255) / 256, 256>>>(w_qkv, 3 * CC * CC / 4);
    k_tc_gemm<0><<<dim3(3 * CC / 128, ROWS / 128), 256, GSMEM>>>(3 * CC, CC, nullptr);

    k_attn<<<dim3(BB * 4, HH), 256, ATT_SMEM>>>(rpb);

    // proj (writes fp32 xattn + bf16 split for pw1)
    k_cvt_w<<<(CC * CC / 4 + 255) / 256, 256>>>(w_proj, CC * CC / 4);
    k_tc_gemm<1><<<dim3(CC / 128, ROWS / 128), 256, GSMEM>>>(CC, CC, b_proj);

    // pw1 (+fused h1 stats)
    k_cvt_w<<<(HIDN * CC / 4 + 255) / 256, 256>>>(pw1_w, HIDN * CC / 4);
    k_zero_stats<<<(HIDN + 255) / 256, 256>>>();
    k_tc_gemm<2><<<dim3(HIDN / 128, ROWS / 128), 256, GSMEM>>>(HIDN, CC, nullptr);
    k_bnprep<<<(HIDN + 255) / 256, 256>>>(bn1_g, bn1_b, HIDN);

    k_dwconv<<<(ROWS * (HIDN / 4) + 255) / 256, 256>>>(dw_w);

    // bn2 stats -> params
    k_zero_stats<<<(HIDN + 255) / 256, 256>>>();
    k_colstats_h2<<<dim3(HIDN / 128, ROWS / 128), 128>>>(HIDN);
    k_bnprep<<<(HIDN + 255) / 256, 256>>>(bn2_g, bn2_b, HIDN);

    k_sepool<<<dim3(BB, HIDN / 128), 128>>>();
    k_semlp1<<<CC / 128, 256>>>(se_w1, se_b1);
    k_semlp2<<<HIDN / 128, 256>>>(se_w2, se_b2);

    // pw2 (+fused h3 stats)
    k_cvt_a_se<<<(ROWS * (HIDN / 4) + 255) / 256, 256>>>();
    k_cvt_w<<<(CC * HIDN / 4 + 255) / 256, 256>>>(pw2_w, CC * HIDN / 4);
    k_zero_stats<<<(HIDN + 255) / 256, 256>>>();
    k_tc_gemm<3><<<dim3(CC / 128, ROWS / 128), 256, GSMEM>>>(CC, HIDN, nullptr);

    k_final<<<(ROWS * (CC / 4) + 255) / 256, 256>>>(bn3_g, bn3_b, out);
    (void)in_sizes; (void)n_in; (void)out_size;
}

// round 17
// speedup vs baseline: 1.1544x; 1.0522x over previous
#include <cuda_runtime.h>
#include <cuda_bf16.h>
#include <cstdint>

// ---------------- problem constants ----------------
#define BB    32
#define PP    14
#define CC    768
#define HH    12
#define HD    64
#define HIDN  3072
#define NWIN  49
#define NPIX  196
#define ROWS  6272         // 32*196

// ---------------- scratch ----------------
__device__ float g_qkv  [(size_t)ROWS * 3 * CC];
__device__ float g_xattn[(size_t)ROWS * CC];
__device__ float g_h1   [(size_t)ROWS * HIDN];
__device__ float g_h2   [(size_t)ROWS * HIDN];
__device__ float g_h3   [(size_t)ROWS * CC];
__device__ float g_s1   [HIDN];
__device__ float g_s2   [HIDN];
__device__ float g_semean [BB * HIDN];
__device__ float g_sehid  [BB * CC];
__device__ float g_sescale[BB * HIDN];
__device__ float g_bnsc [HIDN];
__device__ float g_bnsh [HIDN];
// bf16 split buffers
__device__ __nv_bfloat16 g_ahi[(size_t)ROWS * HIDN];
__device__ __nv_bfloat16 g_alo[(size_t)ROWS * HIDN];
__device__ __nv_bfloat16 g_bhi[(size_t)ROWS * CC];
__device__ __nv_bfloat16 g_blo[(size_t)ROWS * CC];
__device__ __nv_bfloat16 g_whi[(size_t)HIDN * CC];
__device__ __nv_bfloat16 g_wlo[(size_t)HIDN * CC];

__device__ __forceinline__ int reg3(int r) { return r < 7 ? 0 : (r < 11 ? 1 : 2); }
__device__ __forceinline__ float hsw(float x) { return x * __saturatef((x + 3.f) * (1.f / 6.f)); }
__device__ __forceinline__ void split2(float a, float b, uint32_t& hi, uint32_t& lo) {
    __nv_bfloat16 ha = __float2bfloat16(a), hb = __float2bfloat16(b);
    __nv_bfloat16 la = __float2bfloat16(a - __bfloat162float(ha));
    __nv_bfloat16 lb = __float2bfloat16(b - __bfloat162float(hb));
    __nv_bfloat162 H = __halves2bfloat162(ha, hb), L = __halves2bfloat162(la, lb);
    hi = *(uint32_t*)&H; lo = *(uint32_t*)&L;
}
__device__ __forceinline__ uint32_t s2u(const void* p) {
    uint32_t a;
    asm("{ .reg .u64 t; cvta.to.shared.u64 t, %1; cvt.u32.u64 %0, t; }" : "=r"(a) : "l"(p));
    return a;
}
#define CPA16(dst, src) asm volatile("cp.async.cg.shared.global [%0], [%1], 16;" :: "r"(dst), "l"(src) : "memory")
#define CPA_COMMIT()    asm volatile("cp.async.commit_group;" ::: "memory")
#define CPA_WAIT1()     asm volatile("cp.async.wait_group 1;" ::: "memory")
#define CPA_WAIT0()     asm volatile("cp.async.wait_group 0;" ::: "memory")

__device__ __forceinline__ void ldmA(uint32_t* r, uint32_t addr) {
    asm volatile("ldmatrix.sync.aligned.m8n8.x4.shared.b16 {%0,%1,%2,%3}, [%4];"
                 : "=r"(r[0]), "=r"(r[1]), "=r"(r[2]), "=r"(r[3]) : "r"(addr));
}
__device__ __forceinline__ void ldmB(uint32_t* r, uint32_t addr) {
    asm volatile("ldmatrix.sync.aligned.m8n8.x2.shared.b16 {%0,%1}, [%2];"
                 : "=r"(r[0]), "=r"(r[1]) : "r"(addr));
}
__device__ __forceinline__ void mma16816(float* c, const uint32_t* a, const uint32_t* b) {
    asm volatile("mma.sync.aligned.m16n8k16.row.col.f32.bf16.bf16.f32 "
                 "{%0,%1,%2,%3}, {%4,%5,%6,%7}, {%8,%9}, {%0,%1,%2,%3};"
                 : "+f"(c[0]), "+f"(c[1]), "+f"(c[2]), "+f"(c[3])
                 : "r"(a[0]), "r"(a[1]), "r"(a[2]), "r"(a[3]), "r"(b[0]), "r"(b[1]));
}

// ---------------- cls passthrough ----------------
__global__ void k_cls(const float* __restrict__ x, float* __restrict__ out) {
    int i = blockIdx.x * blockDim.x + threadIdx.x;
    if (i >= BB * CC) return;
    int b = i / CC, c = i % CC;
    out[(size_t)b * 197 * CC + c] = x[(size_t)b * 197 * CC + c];
}

// ---------------- copy pixel tokens, split to bf16 hi/lo ----------------
__global__ void k_copyx(const float* __restrict__ x) {
    int i = blockIdx.x * blockDim.x + threadIdx.x;
    if (i >= ROWS * (CC / 4)) return;
    int c4  = i % (CC / 4);
    int row = i / (CC / 4);
    int b = row / NPIX, p = row % NPIX;
    float4 v = *(const float4*)(x + ((size_t)b * 197 + 1 + p) * CC + c4 * 4);
    uint2 hi, lo;
    split2(v.x, v.y, hi.x, lo.x);
    split2(v.z, v.w, hi.y, lo.y);
    *(uint2*)(g_ahi + (size_t)row * CC + c4 * 4) = hi;
    *(uint2*)(g_alo + (size_t)row * CC + c4 * 4) = lo;
}

// ---------------- weight split (vectorized x4) ----------------
__global__ void k_cvt_w(const float* __restrict__ w, int total4) {
    int i = blockIdx.x * blockDim.x + threadIdx.x;
    if (i >= total4) return;
    float4 v = *(const float4*)(w + (size_t)i * 4);
    uint2 hi, lo;
    split2(v.x, v.y, hi.x, lo.x);
    split2(v.z, v.w, hi.y, lo.y);
    *(uint2*)(g_whi + (size_t)i * 4) = hi;
    *(uint2*)(g_wlo + (size_t)i * 4) = lo;
}

// ---------------- SE-scaled + BN2/hswish split (pw2 input) ----------------
__global__ void k_cvt_a_se() {
    int i = blockIdx.x * blockDim.x + threadIdx.x;
    if (i >= ROWS * (HIDN / 4)) return;
    int c4 = (i % (HIDN / 4)) * 4;
    int b  = i / (NPIX * (HIDN / 4));
    float4 v  = *(float4*)(g_h2 + (size_t)i * 4);
    float4 sc = *(float4*)(g_bnsc + c4);
    float4 sh = *(float4*)(g_bnsh + c4);
    float4 ss = *(float4*)(g_sescale + (size_t)b * HIDN + c4);
    float a0 = hsw(v.x * sc.x + sh.x) * ss.x;
    float a1 = hsw(v.y * sc.y + sh.y) * ss.y;
    float a2 = hsw(v.z * sc.z + sh.z) * ss.z;
    float a3 = hsw(v.w * sc.w + sh.w) * ss.w;
    uint2 hi, lo;
    split2(a0, a1, hi.x, lo.x);
    split2(a2, a3, hi.y, lo.y);
    *(uint2*)(g_ahi + (size_t)i * 4) = hi;
    *(uint2*)(g_alo + (size_t)i * 4) = lo;
}

// ---------------- HMMA GEMM: C[M,N] = A[M,K] @ W[N,K]^T (bf16 3-pass split) ---
// 128x128 CTA tile, BK=32, 8 warps (2x4), warp tile 64x32.
// 2-stage cp.async pipeline, 80KB smem -> 2 CTAs/SM. Loads interleaved with
// MMA groups so LDSM hides under the previous pass's MMAs.
// MODE: 0:qkv 1:xattn(+bias, +split out) 2:h1(+stats) 3:h3(+stats)
#define TS   40
#define TILE (128 * TS)
#define STG  (4 * TILE)
#define GSMEM (2 * STG * 2)        // 81920 B

template <int MODE>
__global__ __launch_bounds__(256, 2)
void k_tc_gemm(int N, int K, const float* __restrict__ bias) {
    extern __shared__ __nv_bfloat16 smem[];
    const uint32_t sb = s2u(smem);
    const int tid = threadIdx.x, wid = tid >> 5, lane = tid & 31;
    const int nBase = blockIdx.x * 128, mBase = blockIdx.y * 128;
    const int KC = K >> 5;

    const __nv_bfloat16* Ahi = (MODE == 1) ? g_bhi : g_ahi;
    const __nv_bfloat16* Alo = (MODE == 1) ? g_blo : g_alo;
    float* Cmat = (MODE == 0) ? g_qkv : (MODE == 1) ? g_xattn : (MODE == 2) ? g_h1 : g_h3;

    __shared__ float ssum[128], ssq[128];
    if (MODE >= 2 && tid < 128) { ssum[tid] = 0.f; ssq[tid] = 0.f; }

    int cs[8], cr[8], ct[8];
#pragma unroll
    for (int j = 0; j < 8; j++) {
        int s = tid + j * 256;
        ct[j] = s >> 9;
        cr[j] = (s >> 2) & 127;
        cs[j] = s & 3;
    }

    auto issue_stage = [&](int kc, int stg) {
#pragma unroll
        for (int j = 0; j < 8; j++) {
            int t = ct[j], r = cr[j], c4 = cs[j];
            const __nv_bfloat16* src = (t == 0) ? Ahi : (t == 1) ? Alo : (t == 2) ? g_whi : g_wlo;
            int rowg = ((t < 2) ? mBase : nBase) + r;
            const __nv_bfloat16* gp = src + (size_t)rowg * K + (kc << 5) + (c4 << 3);
            uint32_t dst = sb + (uint32_t)(stg * STG + t * TILE + r * TS + (c4 << 3)) * 2;
            CPA16(dst, gp);
        }
        CPA_COMMIT();
    };

    float acc[4][4][4];
#pragma unroll
    for (int mi = 0; mi < 4; mi++)
#pragma unroll
        for (int ni = 0; ni < 4; ni++)
#pragma unroll
            for (int c = 0; c < 4; c++) acc[mi][ni][c] = 0.f;

    const int m0 = (wid >> 2) * 64;
    const int n0 = (wid & 3) * 32;
    const int arow = (lane & 15);
    const int akb  = (lane >> 4) * 8;
    const int l16  = lane & 15;
    const int brow = (l16 & 7);
    const int bkb  = (l16 >> 3) * 8;

    issue_stage(0, 0);

    for (int kc = 0; kc < KC; kc++) {
        if (kc + 1 < KC) { issue_stage(kc + 1, (kc + 1) & 1); CPA_WAIT1(); }
        else             { CPA_WAIT0(); }
        __syncthreads();

        const uint32_t base = sb + (uint32_t)((kc & 1) * STG) * 2;
        const uint32_t bAh = base;
        const uint32_t bAl = base + TILE * 2;
        const uint32_t bWh = base + 2 * TILE * 2;
        const uint32_t bWl = base + 3 * TILE * 2;

#pragma unroll
        for (int ks = 0; ks < 2; ks++) {
            const uint32_t ak = (uint32_t)(ks * 16 + akb) * 2;
            const uint32_t bk = (uint32_t)(ks * 16 + bkb) * 2;
            uint32_t ah[4][4], al[4][4], bh[4][2], bl[4][2];
            // group 1 operands
#pragma unroll
            for (int ni = 0; ni < 4; ni++)
                ldmB(bh[ni], bWh + (uint32_t)((n0 + ni * 8 + brow) * TS) * 2 + bk);
#pragma unroll
            for (int mi = 0; mi < 4; mi++)
                ldmA(ah[mi], bAh + (uint32_t)((m0 + mi * 16 + arow) * TS) * 2 + ak);
            // prefetch group 2's B
#pragma unroll
            for (int ni = 0; ni < 4; ni++)
                ldmB(bl[ni], bWl + (uint32_t)((n0 + ni * 8 + brow) * TS) * 2 + bk);
            // MMA group 1 (ah*bh)
#pragma unroll
            for (int mi = 0; mi < 4; mi++)
#pragma unroll
                for (int ni = 0; ni < 4; ni++) mma16816(acc[mi][ni], ah[mi], bh[ni]);
            // prefetch group 3's A
#pragma unroll
            for (int mi = 0; mi < 4; mi++)
                ldmA(al[mi], bAl + (uint32_t)((m0 + mi * 16 + arow) * TS) * 2 + ak);
            // MMA group 2 (ah*bl)
#pragma unroll
            for (int mi = 0; mi < 4; mi++)
#pragma unroll
                for (int ni = 0; ni < 4; ni++) mma16816(acc[mi][ni], ah[mi], bl[ni]);
            // MMA group 3 (al*bh)
#pragma unroll
            for (int mi = 0; mi < 4; mi++)
#pragma unroll
                for (int ni = 0; ni < 4; ni++) mma16816(acc[mi][ni], al[mi], bh[ni]);
        }
        __syncthreads();   // protect this stage's buffer before it is re-issued
    }

    const int gq = lane >> 2, gr = (lane & 3) * 2;
#pragma unroll
    for (int mi = 0; mi < 4; mi++) {
        int rowA = mBase + m0 + mi * 16 + gq;
#pragma unroll
        for (int ni = 0; ni < 4; ni++) {
            int col = nBase + n0 + ni * 8 + gr;
            float b0 = 0.f, b1 = 0.f;
            if (MODE == 1) { b0 = bias[col]; b1 = bias[col + 1]; }
            float v00 = acc[mi][ni][0] + b0, v01 = acc[mi][ni][1] + b1;
            float v10 = acc[mi][ni][2] + b0, v11 = acc[mi][ni][3] + b1;
            *(float2*)(Cmat + (size_t)rowA * N + col) = make_float2(v00, v01);
            *(float2*)(Cmat + (size_t)(rowA + 8) * N + col) = make_float2(v10, v11);
            if (MODE == 1) {
                uint32_t hi, lo;
                split2(v00, v01, hi, lo);
                *(uint32_t*)(g_ahi + (size_t)rowA * N + col) = hi;
                *(uint32_t*)(g_alo + (size_t)rowA * N + col) = lo;
                split2(v10, v11, hi, lo);
                *(uint32_t*)(g_ahi + (size_t)(rowA + 8) * N + col) = hi;
                *(uint32_t*)(g_alo + (size_t)(rowA + 8) * N + col) = lo;
            }
        }
    }
    if (MODE >= 2) {   // fused BN column stats
        __syncthreads();
#pragma unroll
        for (int ni = 0; ni < 4; ni++) {
            int lc = n0 + ni * 8 + gr;
            float s0 = 0.f, q0 = 0.f, s1 = 0.f, q1 = 0.f;
#pragma unroll
            for (int mi = 0; mi < 4; mi++) {
                float v00 = acc[mi][ni][0], v01 = acc[mi][ni][1];
                float v10 = acc[mi][ni][2], v11 = acc[mi][ni][3];
                s0 += v00 + v10; q0 += v00 * v00 + v10 * v10;
                s1 += v01 + v11; q1 += v01 * v01 + v11 * v11;
            }
            atomicAdd(&ssum[lc], s0);     atomicAdd(&ssq[lc], q0);
            atomicAdd(&ssum[lc + 1], s1); atomicAdd(&ssq[lc + 1], q1);
        }
        __syncthreads();
        if (tid < 128) {
            atomicAdd(&g_s1[nBase + tid], ssum[tid]);
            atomicAdd(&g_s2[nBase + tid], ssq[tid]);
        }
    }
    (void)bias;
}

// ---------------- fused window attention (register-tiled) ----------------
#define AT_ST 68
#define ATT_SMEM ((3 * NWIN * AT_ST + 50 * 50) * 4)
__global__ __launch_bounds__(256) void k_attn(const float* __restrict__ rpb) {
    extern __shared__ float asmem[];
    float* qs = asmem;
    float* ks = qs + NWIN * AT_ST;
    float* vs = ks + NWIN * AT_ST;
    float* sc = vs + NWIN * AT_ST;
    __shared__ int prow[NWIN];
    __shared__ int lab [NWIN];

    const int bw = blockIdx.x;
    const int h  = blockIdx.y;
    const int tid = threadIdx.x;
    const int b = bw >> 2, w = bw & 3;

    if (tid < NWIN) {
        int rr = (w >> 1) * 7 + tid / 7;
        int cc = (w & 1) * 7 + tid % 7;
        prow[tid] = b * NPIX + ((rr + 3) % 14) * 14 + ((cc + 3) % 14);
        lab[tid]  = reg3(rr) * 3 + reg3(cc);
    }
    __syncthreads();

    for (int idx = tid; idx < NWIN * HD; idx += 256) {
        int t = idx >> 6, d = idx & 63;
        const float* base = g_qkv + (size_t)prow[t] * (3 * CC) + h * HD + d;
        qs[t * AT_ST + d] = base[0];
        ks[t * AT_ST + d] = base[CC];
        vs[t * AT_ST + d] = base[2 * CC];
    }
    __syncthreads();

    if (tid < 169) {
        const int tq = (tid / 13) * 4, tk = (tid % 13) * 4;
        float a[4][4];
#pragma unroll
        for (int i = 0; i < 4; i++)
#pragma unroll
            for (int j = 0; j < 4; j++) a[i][j] = 0.f;
#pragma unroll
        for (int d4 = 0; d4 < 16; d4++) {
            float4 qv[4], kv[4];
#pragma unroll
            for (int j = 0; j < 4; j++) {
                qv[j] = *(float4*)&qs[min(tq + j, 48) * AT_ST + d4 * 4];
                kv[j] = *(float4*)&ks[min(tk + j, 48) * AT_ST + d4 * 4];
            }
#pragma unroll
            for (int i = 0; i < 4; i++)
#pragma unroll
                for (int j = 0; j < 4; j++)
                    a[i][j] += qv[i].x * kv[j].x + qv[i].y * kv[j].y
                             + qv[i].z * kv[j].z + qv[i].w * kv[j].w;
        }
#pragma unroll
        for (int i = 0; i < 4; i++) {
            int qi = tq + i;
            if (qi >= NWIN) break;
            int qr = qi / 7, qc = qi % 7;
#pragma unroll
            for (int j = 0; j < 4; j++) {
                int ki = tk + j;
                if (ki >= NWIN) continue;
                int kr = ki / 7, kc = ki % 7;
                float v = a[i][j] * 0.125f + rpb[((qr - kr + 6) * 13 + (qc - kc + 6)) * HH + h];
                if (lab[qi] != lab[ki]) v -= 100.f;
                sc[qi * 50 + ki] = v;
            }
        }
    }
    __syncthreads();

    if (tid < NWIN) {
        float m = -1e30f;
        for (int k = 0; k < NWIN; k++) m = fmaxf(m, sc[tid * 50 + k]);
        float sum = 0.f;
        for (int k = 0; k < NWIN; k++) {
            float e = expf(sc[tid * 50 + k] - m);
            sc[tid * 50 + k] = e; sum += e;
        }
        float inv = 1.f / sum;
        for (int k = 0; k < NWIN; k++) sc[tid * 50 + k] *= inv;
    }
    __syncthreads();

    if (tid < 200) {
        const int tq = (tid / 8) * 2, d8 = (tid % 8) * 8;
        float a0[8], a1[8];
#pragma unroll
        for (int j = 0; j < 8; j++) { a0[j] = 0.f; a1[j] = 0.f; }
        for (int k = 0; k < NWIN; k++) {
            float s0 = sc[tq * 50 + k];
            float s1 = sc[(tq + 1) * 50 + k];
            float4 va = *(float4*)&vs[k * AT_ST + d8];
            float4 vb = *(float4*)&vs[k * AT_ST + d8 + 4];
            a0[0] += s0 * va.x; a0[1] += s0 * va.y; a0[2] += s0 * va.z; a0[3] += s0 * va.w;
            a0[4] += s0 * vb.x; a0[5] += s0 * vb.y; a0[6] += s0 * vb.z; a0[7] += s0 * vb.w;
            a1[0] += s1 * va.x; a1[1] += s1 * va.y; a1[2] += s1 * va.z; a1[3] += s1 * va.w;
            a1[4] += s1 * vb.x; a1[5] += s1 * vb.y; a1[6] += s1 * vb.z; a1[7] += s1 * vb.w;
        }
#pragma unroll
        for (int r = 0; r < 2; r++) {
            int qi = tq + r;
            if (qi >= NWIN) continue;
            float* av = r ? a1 : a0;
            size_t off = (size_t)prow[qi] * CC + h * HD + d8;
#pragma unroll
            for (int j = 0; j < 4; j++) {
                uint32_t hi, lo;
                split2(av[2 * j], av[2 * j + 1], hi, lo);
                *(uint32_t*)(g_bhi + off + 2 * j) = hi;
                *(uint32_t*)(g_blo + off + 2 * j) = lo;
            }
        }
    }
}

// ---------------- BN stats ----------------
__global__ void k_zero_stats() {
    int i = blockIdx.x * blockDim.x + threadIdx.x;
    if (i < HIDN) { g_s1[i] = 0.f; g_s2[i] = 0.f; }
}
__global__ void k_bnprep(const float* __restrict__ g, const float* __restrict__ b, int N) {
    int ch = blockIdx.x * blockDim.x + threadIdx.x;
    if (ch >= N) return;
    float m   = g_s1[ch] * (1.f / ROWS);
    float var = fmaxf(g_s2[ch] * (1.f / ROWS) - m * m, 0.f);
    float sc  = g[ch] * rsqrtf(var + 1e-5f);
    g_bnsc[ch] = sc;
    g_bnsh[ch] = b[ch] - m * sc;
}

// ---------------- tiled depthwise 3x3: bn1+hswish at load, bn2 stats fused ----
// block = (channel-chunk of 16 c4, batch). smem tile = 196 pixels x 16 float4.
#define DW_CH 16
#define DW_SMEM (NPIX * DW_CH * 16 + 256 * 8 * 4)   // 50176 + 8192 B
__global__ __launch_bounds__(256) void k_dwconv(const float* __restrict__ w) {
    extern __shared__ float dsm[];
    float4* tile = (float4*)dsm;                     // [196][16]
    float*  red  = dsm + NPIX * DW_CH * 4;           // [256][8]
    const int chunk = blockIdx.x;                    // 0..47
    const int b     = blockIdx.y;                    // 0..31
    const int tid = threadIdx.x;
    const int c4g = chunk * DW_CH;

    // load tile with bn1+hswish applied once per element
    for (int idx = tid; idx < NPIX * DW_CH; idx += 256) {
        int pix = idx >> 4, c4l = idx & 15;
        int c4 = c4g + c4l;
        float4 v  = *(const float4*)(g_h1 + ((size_t)(b * NPIX + pix)) * HIDN + c4 * 4);
        float4 sc = *(const float4*)(g_bnsc + c4 * 4);
        float4 sh = *(const float4*)(g_bnsh + c4 * 4);
        v.x = hsw(v.x * sc.x + sh.x);
        v.y = hsw(v.y * sc.y + sh.y);
        v.z = hsw(v.z * sc.z + sh.z);
        v.w = hsw(v.w * sc.w + sh.w);
        tile[idx] = v;
    }
    __syncthreads();

    const int c4l  = tid & 15;
    const int pgrp = tid >> 4;                       // 0..15
    const int c4 = c4g + c4l;

    float wt[4][9];
#pragma unroll
    for (int j = 0; j < 4; j++)
#pragma unroll
        for (int t = 0; t < 9; t++) wt[j][t] = w[(size_t)(c4 * 4 + j) * 9 + t];

    float s1a[4] = {0.f, 0.f, 0.f, 0.f}, s2a[4] = {0.f, 0.f, 0.f, 0.f};
    for (int p = pgrp; p < NPIX; p += 16) {
        int r = p / 14, c = p % 14;
        float acc[4] = {0.f, 0.f, 0.f, 0.f};
#pragma unroll
        for (int dr = 0; dr < 3; dr++) {
            int rr = r + dr - 1;
            if (rr < 0 || rr > 13) continue;
#pragma unroll
            for (int dc = 0; dc < 3; dc++) {
                int cc = c + dc - 1;
                if (cc < 0 || cc > 13) continue;
                float4 v = tile[(rr * 14 + cc) * DW_CH + c4l];
                acc[0] += v.x * wt[0][dr * 3 + dc];
                acc[1] += v.y * wt[1][dr * 3 + dc];
                acc[2] += v.z * wt[2][dr * 3 + dc];
                acc[3] += v.w * wt[3][dr * 3 + dc];
            }
        }
        *(float4*)(g_h2 + ((size_t)(b * NPIX + p)) * HIDN + c4 * 4) =
            make_float4(acc[0], acc[1], acc[2], acc[3]);
#pragma unroll
        for (int j = 0; j < 4; j++) { s1a[j] += acc[j]; s2a[j] += acc[j] * acc[j]; }
    }
    // reduce bn2 stats across the 16 pixel groups
#pragma unroll
    for (int j = 0; j < 4; j++) { red[tid * 8 + j] = s1a[j]; red[tid * 8 + 4 + j] = s2a[j]; }
    __syncthreads();
    if (pgrp == 0) {
#pragma unroll
        for (int g = 1; g < 16; g++)
#pragma unroll
            for (int j = 0; j < 4; j++) {
                s1a[j] += red[(g * 16 + c4l) * 8 + j];
                s2a[j] += red[(g * 16 + c4l) * 8 + 4 + j];
            }
#pragma unroll
        for (int j = 0; j < 4; j++) {
            atomicAdd(&g_s1[c4 * 4 + j], s1a[j]);
            atomicAdd(&g_s2[c4 * 4 + j], s2a[j]);
        }
    }
}

// ---------------- SE: pool (fused BN2+hswish) + weight-stationary MLP ---------
__global__ void k_sepool() {
    int b  = blockIdx.x;
    int ch = blockIdx.y * 128 + threadIdx.x;
    float sc = g_bnsc[ch], sh = g_bnsh[ch];
    float s = 0.f;
    for (int p = 0; p < NPIX; p++)
        s += hsw(g_h2[((size_t)b * NPIX + p) * HIDN + ch] * sc + sh);
    g_semean[b * HIDN + ch] = s * (1.f / NPIX);
}
__global__ __launch_bounds__(256) void k_semlp1(
    const float* __restrict__ w1, const float* __restrict__ b1)
{
    __shared__ float st[32][128];
    const int half = threadIdx.x >> 7;
    const int jloc = threadIdx.x & 127;
    const int j = blockIdx.x * 128 + jloc;
    float acc[16];
#pragma unroll
    for (int b = 0; b < 16; b++) acc[b] = 0.f;
    for (int k0 = 0; k0 < HIDN; k0 += 128) {
        for (int t = threadIdx.x; t < 32 * 128; t += 256) {
            int b = t >> 7, k = t & 127;
            st[b][k] = g_semean[(size_t)b * HIDN + k0 + k];
        }
        __syncthreads();
        const float* wr = w1 + (size_t)j * HIDN + k0;
#pragma unroll 4
        for (int k = 0; k < 128; k++) {
            float wv = wr[k];
#pragma unroll
            for (int b = 0; b < 16; b++) acc[b] += wv * st[half * 16 + b][k];
        }
        __syncthreads();
    }
    float bj = b1[j];
#pragma unroll
    for (int b = 0; b < 16; b++)
        g_sehid[(size_t)(half * 16 + b) * CC + j] = fmaxf(acc[b] + bj, 0.f);
}
__global__ __launch_bounds__(256) void k_semlp2(
    const float* __restrict__ w2, const float* __restrict__ b2)
{
    __shared__ float st[32][128];
    const int half = threadIdx.x >> 7;
    const int jloc = threadIdx.x & 127;
    const int j = blockIdx.x * 128 + jloc;
    float acc[16];
#pragma unroll
    for (int b = 0; b < 16; b++) acc[b] = 0.f;
    for (int k0 = 0; k0 < CC; k0 += 128) {
        for (int t = threadIdx.x; t < 32 * 128; t += 256) {
            int b = t >> 7, k = t & 127;
            st[b][k] = g_sehid[(size_t)b * CC + k0 + k];
        }
        __syncthreads();
        const float* wr = w2 + (size_t)j * CC + k0;
#pragma unroll 4
        for (int k = 0; k < 128; k++) {
            float wv = wr[k];
#pragma unroll
            for (int b = 0; b < 16; b++) acc[b] += wv * st[half * 16 + b][k];
        }
        __syncthreads();
    }
    float bj = b2[j];
#pragma unroll
    for (int b = 0; b < 16; b++)
        g_sescale[(size_t)(half * 16 + b) * HIDN + j] =
            fminf(fmaxf(acc[b] + bj + 3.f, 0.f), 6.f) * (1.f / 6.f);
}

// ---------------- final: bn3 + residual + write out ----------------
__global__ void k_final(const float* __restrict__ g, const float* __restrict__ bb,
                        float* __restrict__ out) {
    int i = blockIdx.x * blockDim.x + threadIdx.x;
    if (i >= ROWS * (CC / 4)) return;
    int c4  = (i % (CC / 4)) * 4;
    int pix = i / (CC / 4);
    int b = pix / NPIX, p = pix % NPIX;
    float4 hv = *(float4*)(g_h3 + (size_t)i * 4);
    float4 xv = *(float4*)(g_xattn + (size_t)i * 4);
    float h[4] = { hv.x, hv.y, hv.z, hv.w };
    float x[4] = { xv.x, xv.y, xv.z, xv.w };
#pragma unroll
    for (int j = 0; j < 4; j++) {
        int ch = c4 + j;
        float m   = g_s1[ch] * (1.f / ROWS);
        float var = fmaxf(g_s2[ch] * (1.f / ROWS) - m * m, 0.f);
        x[j] += (h[j] - m) * rsqrtf(var + 1e-5f) * g[ch] + bb[ch];
    }
    float* dst = out + ((size_t)b * 197 + 1 + p) * CC + c4;
    *(float4*)dst = make_float4(x[0], x[1], x[2], x[3]);
}

// ---------------- launch ----------------
extern "C" void kernel_launch(void* const* d_in, const int* in_sizes, int n_in,
                              void* d_out, int out_size) {
    int idx[18];
    for (int i = 0; i < 18; i++) idx[i] = i;
    const int X_ELEMS = BB * 197 * CC;
    if (n_in == 18 && in_sizes[0] != X_ELEMS && in_sizes[17] == X_ELEMS) {
        const int m[18] = {17, 16, 15, 0, 10, 8, 2, 1, 7, 4, 3, 13, 11, 14, 12, 9, 6, 5};
        for (int i = 0; i < 18; i++) idx[i] = m[i];
    }

    const float* x      = (const float*)d_in[idx[0]];
    const float* w_qkv  = (const float*)d_in[idx[1]];
    const float* w_proj = (const float*)d_in[idx[2]];
    const float* b_proj = (const float*)d_in[idx[3]];
    const float* rpb    = (const float*)d_in[idx[4]];
    const float* pw1_w  = (const float*)d_in[idx[5]];
    const float* bn1_g  = (const float*)d_in[idx[6]];
    const float* bn1_b  = (const float*)d_in[idx[7]];
    const float* dw_w   = (const float*)d_in[idx[8]];
    const float* bn2_g  = (const float*)d_in[idx[9]];
    const float* bn2_b  = (const float*)d_in[idx[10]];
    const float* se_w1  = (const float*)d_in[idx[11]];
    const float* se_b1  = (const float*)d_in[idx[12]];
    const float* se_w2  = (const float*)d_in[idx[13]];
    const float* se_b2  = (const float*)d_in[idx[14]];
    const float* pw2_w  = (const float*)d_in[idx[15]];
    const float* bn3_g  = (const float*)d_in[idx[16]];
    const float* bn3_b  = (const float*)d_in[idx[17]];
    float* out = (float*)d_out;

    cudaFuncSetAttribute(k_tc_gemm<0>, cudaFuncAttributeMaxDynamicSharedMemorySize, GSMEM);
    cudaFuncSetAttribute(k_tc_gemm<1>, cudaFuncAttributeMaxDynamicSharedMemorySize, GSMEM);
    cudaFuncSetAttribute(k_tc_gemm<2>, cudaFuncAttributeMaxDynamicSharedMemorySize, GSMEM);
    cudaFuncSetAttribute(k_tc_gemm<3>, cudaFuncAttributeMaxDynamicSharedMemorySize, GSMEM);
    cudaFuncSetAttribute(k_attn, cudaFuncAttributeMaxDynamicSharedMemorySize, ATT_SMEM);
    cudaFuncSetAttribute(k_dwconv, cudaFuncAttributeMaxDynamicSharedMemorySize, DW_SMEM);

    k_cls<<<(BB * CC + 255) / 256, 256>>>(x, out);
    k_copyx<<<(ROWS * (CC / 4) + 255) / 256, 256>>>(x);

    // QKV
    k_cvt_w<<<(3 * CC * CC / 4 + 255) / 256, 256>>>(w_qkv, 3 * CC * CC / 4);
    k_tc_gemm<0><<<dim3(3 * CC / 128, ROWS / 128), 256, GSMEM>>>(3 * CC, CC, nullptr);

    k_attn<<<dim3(BB * 4, HH), 256, ATT_SMEM>>>(rpb);

    // proj (writes fp32 xattn + bf16 split for pw1)
    k_cvt_w<<<(CC * CC / 4 + 255) / 256, 256>>>(w_proj, CC * CC / 4);
    k_tc_gemm<1><<<dim3(CC / 128, ROWS / 128), 256, GSMEM>>>(CC, CC, b_proj);

    // pw1 (+fused h1 stats)
    k_cvt_w<<<(HIDN * CC / 4 + 255) / 256, 256>>>(pw1_w, HIDN * CC / 4);
    k_zero_stats<<<(HIDN + 255) / 256, 256>>>();
    k_tc_gemm<2><<<dim3(HIDN / 128, ROWS / 128), 256, GSMEM>>>(HIDN, CC, nullptr);
    k_bnprep<<<(HIDN + 255) / 256, 256>>>(bn1_g, bn1_b, HIDN);

    // dwconv (bn1+hswish fused at load, bn2 stats fused in epilogue)
    k_zero_stats<<<(HIDN + 255) / 256, 256>>>();
    k_dwconv<<<dim3(HIDN / (DW_CH * 4), BB), 256, DW_SMEM>>>(dw_w);
    k_bnprep<<<(HIDN + 255) / 256, 256>>>(bn2_g, bn2_b, HIDN);

    k_sepool<<<dim3(BB, HIDN / 128), 128>>>();
    k_semlp1<<<CC / 128, 256>>>(se_w1, se_b1);
    k_semlp2<<<HIDN / 128, 256>>>(se_w2, se_b2);

    // pw2 (+fused h3 stats)
    k_cvt_a_se<<<(ROWS * (HIDN / 4) + 255) / 256, 256>>>();
    k_cvt_w<<<(CC * HIDN / 4 + 255) / 256, 256>>>(pw2_w, CC * HIDN / 4);
    k_zero_stats<<<(HIDN + 255) / 256, 256>>>();
    k_tc_gemm<3><<<dim3(CC / 128, ROWS / 128), 256, GSMEM>>>(CC, HIDN, nullptr);

    k_final<<<(ROWS * (CC / 4) + 255) / 256, 256>>>(bn3_g, bn3_b, out);
    (void)in_sizes; (void)n_in; (void)out_size;
}